// round 2
// baseline (speedup 1.0000x reference)
#include <cuda_runtime.h>
#include <cstdint>

// Problem dims (fixed for this dataset entry)
#define MTOK 8192   // B*S = 4*2048
#define DDIM 2048   // D
#define FDIM 8192   // F
#define RRANK 16    // LoRA rank

// GEMM tiling
#define BM 128
#define BN 128
#define BK 16
#define TM 8
#define TN 8

// ---------------- scratch (allocation-free: __device__ globals) ----------------
__device__ float g_scratch[(size_t)MTOK * FDIM];   // 256 MB: y1 then x3 (in place)
__device__ float g_t_gate[MTOK * RRANK];
__device__ float g_t_up[MTOK * RRANK];
__device__ float g_t_down[MTOK * RRANK];

// ---------------- LoRA-A projection: T[m,r] = sum_k X[m,k]*A[k,r] ----------------
// One warp per row; optional second (A1,T1) pair computed in the same pass over X.
__global__ __launch_bounds__(256)
void lora_a_kernel(const float* __restrict__ X, int K,
                   const float* __restrict__ A0, float* __restrict__ T0,
                   const float* __restrict__ A1, float* __restrict__ T1)
{
    int m    = blockIdx.x * 8 + (threadIdx.x >> 5);
    int lane = threadIdx.x & 31;

    float acc0[RRANK];
    float acc1[RRANK];
#pragma unroll
    for (int r = 0; r < RRANK; r++) { acc0[r] = 0.f; acc1[r] = 0.f; }

    const float* xr = X + (size_t)m * K;
    const bool dual = (A1 != nullptr);

    for (int k = lane; k < K; k += 32) {
        float x = __ldg(xr + k);
        const float4* a0 = reinterpret_cast<const float4*>(A0 + (size_t)k * RRANK);
#pragma unroll
        for (int q = 0; q < 4; q++) {
            float4 v = __ldg(a0 + q);
            acc0[q*4+0] += x * v.x;
            acc0[q*4+1] += x * v.y;
            acc0[q*4+2] += x * v.z;
            acc0[q*4+3] += x * v.w;
        }
        if (dual) {
            const float4* a1 = reinterpret_cast<const float4*>(A1 + (size_t)k * RRANK);
#pragma unroll
            for (int q = 0; q < 4; q++) {
                float4 v = __ldg(a1 + q);
                acc1[q*4+0] += x * v.x;
                acc1[q*4+1] += x * v.y;
                acc1[q*4+2] += x * v.z;
                acc1[q*4+3] += x * v.w;
            }
        }
    }

    // warp butterfly reduce
#pragma unroll
    for (int r = 0; r < RRANK; r++) {
#pragma unroll
        for (int off = 16; off > 0; off >>= 1) {
            acc0[r] += __shfl_xor_sync(0xffffffffu, acc0[r], off);
            acc1[r] += __shfl_xor_sync(0xffffffffu, acc1[r], off);
        }
    }
    if (lane == 0) {
#pragma unroll
        for (int r = 0; r < RRANK; r++) {
            T0[(size_t)m * RRANK + r] = acc0[r];
            if (dual) T1[(size_t)m * RRANK + r] = acc1[r];
        }
    }
}

// ---------------- tile FMA helper ----------------
__device__ __forceinline__
void mma_tile(float (&acc)[TM][TN],
              const float (&As)[BK][BM], const float (&Bs)[BK][BN],
              int ty, int tx)
{
#pragma unroll
    for (int kk = 0; kk < BK; kk++) {
        float4 a0 = *reinterpret_cast<const float4*>(&As[kk][ty * TM]);
        float4 a1 = *reinterpret_cast<const float4*>(&As[kk][ty * TM + 4]);
        float4 b0 = *reinterpret_cast<const float4*>(&Bs[kk][tx * TN]);
        float4 b1 = *reinterpret_cast<const float4*>(&Bs[kk][tx * TN + 4]);
        float ar[TM] = {a0.x, a0.y, a0.z, a0.w, a1.x, a1.y, a1.z, a1.w};
        float br[TN] = {b0.x, b0.y, b0.z, b0.w, b1.x, b1.y, b1.z, b1.w};
#pragma unroll
        for (int i = 0; i < TM; i++)
#pragma unroll
            for (int j = 0; j < TN; j++)
                acc[i][j] += ar[i] * br[j];
    }
}

// ---------------- GEMM with bias + LoRA-B epilogue tile + optional relu-gate ----------------
// C[m,n] = A[m,:]@B[:,n] + bias[n] + T[m,:]@Lb[:,n]        (Gate == nullptr)
// C[m,n] = relu(Gate[m,n]) * (A@B + bias + T@Lb)           (Gate != nullptr; C may alias Gate)
__global__ __launch_bounds__(256, 2)
void gemm_epi(const float* __restrict__ A, int lda,
              const float* __restrict__ B, int ldb,
              const float* __restrict__ bias,
              const float* __restrict__ T,    // [M, 16]
              const float* __restrict__ Lb,   // [16, N]
              float* __restrict__ C,
              const float* __restrict__ Gate,
              int M, int N, int K)
{
    __shared__ float As[BK][BM];
    __shared__ float Bs[BK][BN];

    const int tid = threadIdx.x;
    const int bm  = blockIdx.y * BM;
    const int bn  = blockIdx.x * BN;

    // loader indices
    const int arow = tid >> 2;          // 0..63   (A tile rows, +64 for second)
    const int acol = (tid & 3) * 4;     // 0,4,8,12
    const int brow = tid >> 5;          // 0..7    (B tile rows, +8 for second)
    const int bcol = (tid & 31) * 4;    // 0..124

    const int ty = tid >> 4;            // 0..15
    const int tx = tid & 15;            // 0..15

    float acc[TM][TN];
#pragma unroll
    for (int i = 0; i < TM; i++)
#pragma unroll
        for (int j = 0; j < TN; j++)
            acc[i][j] = 0.f;

    for (int k0 = 0; k0 < K; k0 += BK) {
#pragma unroll
        for (int h = 0; h < 2; h++) {
            int r = arow + 64 * h;
            float4 v = *reinterpret_cast<const float4*>(
                A + (size_t)(bm + r) * lda + k0 + acol);
            As[acol + 0][r] = v.x;
            As[acol + 1][r] = v.y;
            As[acol + 2][r] = v.z;
            As[acol + 3][r] = v.w;
        }
#pragma unroll
        for (int h = 0; h < 2; h++) {
            int r = brow + 8 * h;
            *reinterpret_cast<float4*>(&Bs[r][bcol]) =
                *reinterpret_cast<const float4*>(B + (size_t)(k0 + r) * ldb + bn + bcol);
        }
        __syncthreads();
        mma_tile(acc, As, Bs, ty, tx);
        __syncthreads();
    }

    // ---- LoRA contribution as one extra BK=16 tile: As <- T^T slice, Bs <- Lb slice ----
#pragma unroll
    for (int h = 0; h < 2; h++) {
        int r = arow + 64 * h;
        float4 v = *reinterpret_cast<const float4*>(T + (size_t)(bm + r) * RRANK + acol);
        As[acol + 0][r] = v.x;
        As[acol + 1][r] = v.y;
        As[acol + 2][r] = v.z;
        As[acol + 3][r] = v.w;
    }
#pragma unroll
    for (int h = 0; h < 2; h++) {
        int r = brow + 8 * h;
        *reinterpret_cast<float4*>(&Bs[r][bcol]) =
            *reinterpret_cast<const float4*>(Lb + (size_t)r * N + bn + bcol);
    }
    __syncthreads();
    mma_tile(acc, As, Bs, ty, tx);

    // ---- epilogue: bias (+ optional relu-gate), vectorized stores ----
#pragma unroll
    for (int i = 0; i < TM; i++) {
        int m = bm + ty * TM + i;
#pragma unroll
        for (int j = 0; j < TN; j += 4) {
            int n = bn + tx * TN + j;
            float4 o;
            o.x = acc[i][j + 0] + bias[n + 0];
            o.y = acc[i][j + 1] + bias[n + 1];
            o.z = acc[i][j + 2] + bias[n + 2];
            o.w = acc[i][j + 3] + bias[n + 3];
            if (Gate != nullptr) {
                float4 g = *reinterpret_cast<const float4*>(Gate + (size_t)m * N + n);
                o.x = fmaxf(g.x, 0.f) * o.x;
                o.y = fmaxf(g.y, 0.f) * o.y;
                o.z = fmaxf(g.z, 0.f) * o.z;
                o.w = fmaxf(g.w, 0.f) * o.w;
            }
            *reinterpret_cast<float4*>(C + (size_t)m * N + n) = o;
        }
    }
}

// ---------------- launcher ----------------
extern "C" void kernel_launch(void* const* d_in, const int* in_sizes, int n_in,
                              void* d_out, int out_size)
{
    const float* x1     = (const float*)d_in[0];
    const float* w_gate = (const float*)d_in[1];
    const float* b_gate = (const float*)d_in[2];
    const float* wga    = (const float*)d_in[3];   // w_gate_lora_a [D,16]
    const float* wgb    = (const float*)d_in[4];   // w_gate_lora_b [16,F]
    const float* w_up   = (const float*)d_in[5];
    const float* b_up   = (const float*)d_in[6];
    const float* wua    = (const float*)d_in[7];
    const float* wub    = (const float*)d_in[8];
    const float* w_down = (const float*)d_in[9];   // [F,D]
    const float* b_down = (const float*)d_in[10];
    const float* wda    = (const float*)d_in[11];  // [F,16]
    const float* wdb    = (const float*)d_in[12];  // [16,D]
    float* out = (float*)d_out;

    float *scratch, *tg, *tu, *td;
    cudaGetSymbolAddress((void**)&scratch, g_scratch);
    cudaGetSymbolAddress((void**)&tg, g_t_gate);
    cudaGetSymbolAddress((void**)&tu, g_t_up);
    cudaGetSymbolAddress((void**)&td, g_t_down);

    // 1) t_gate, t_up = x1 @ lora_a  (single pass over x1)
    lora_a_kernel<<<MTOK / 8, 256>>>(x1, DDIM, wga, tg, wua, tu);

    // 2) y1 = x1@w_gate + b_gate + t_gate@wgb  -> scratch
    gemm_epi<<<dim3(FDIM / BN, MTOK / BM), 256>>>(
        x1, DDIM, w_gate, FDIM, b_gate, tg, wgb, scratch, nullptr,
        MTOK, FDIM, DDIM);

    // 3) x3 = relu(y1) * (x1@w_up + b_up + t_up@wub)  -> scratch (in place)
    gemm_epi<<<dim3(FDIM / BN, MTOK / BM), 256>>>(
        x1, DDIM, w_up, FDIM, b_up, tu, wub, scratch, scratch,
        MTOK, FDIM, DDIM);

    // 4) t_down = x3 @ w_down_lora_a
    lora_a_kernel<<<MTOK / 8, 256>>>(scratch, FDIM, wda, td, nullptr, nullptr);

    // 5) out = x3@w_down + b_down + t_down@wdb
    gemm_epi<<<dim3(DDIM / BN, MTOK / BM), 256>>>(
        scratch, FDIM, w_down, DDIM, b_down, td, wdb, out, nullptr,
        MTOK, DDIM, FDIM);
}

// round 4
// speedup vs baseline: 2.0042x; 2.0042x over previous
#include <cuda_runtime.h>
#include <cuda_bf16.h>
#include <cstdint>

#define MTOK 8192
#define DDIM 2048
#define FDIM 8192
#define RR   16

// ---------------- device scratch (allocation-free) ----------------
__device__ __align__(1024) float         g_y1[(size_t)MTOK * FDIM];
__device__ __align__(1024) __nv_bfloat16 g_x1h[(size_t)MTOK * DDIM];
__device__ __align__(1024) __nv_bfloat16 g_x1l[(size_t)MTOK * DDIM];
__device__ __align__(1024) __nv_bfloat16 g_x3h[(size_t)MTOK * FDIM];
__device__ __align__(1024) __nv_bfloat16 g_x3l[(size_t)MTOK * FDIM];
__device__ __align__(1024) __nv_bfloat16 g_wgh[(size_t)FDIM * DDIM];
__device__ __align__(1024) __nv_bfloat16 g_wgl[(size_t)FDIM * DDIM];
__device__ __align__(1024) __nv_bfloat16 g_wuh[(size_t)FDIM * DDIM];
__device__ __align__(1024) __nv_bfloat16 g_wul[(size_t)FDIM * DDIM];
__device__ __align__(1024) __nv_bfloat16 g_wdh[(size_t)DDIM * FDIM];
__device__ __align__(1024) __nv_bfloat16 g_wdl[(size_t)DDIM * FDIM];
__device__ __align__(1024) __nv_bfloat16 g_lgh[FDIM * RR], g_lgl[FDIM * RR];
__device__ __align__(1024) __nv_bfloat16 g_luh[FDIM * RR], g_lul[FDIM * RR];
__device__ __align__(1024) __nv_bfloat16 g_ldh[DDIM * RR], g_ldl[DDIM * RR];
__device__ __align__(1024) __nv_bfloat16 g_tgh[MTOK * RR], g_tgl[MTOK * RR];
__device__ __align__(1024) __nv_bfloat16 g_tuh[MTOK * RR], g_tul[MTOK * RR];
__device__ __align__(1024) __nv_bfloat16 g_tdh[MTOK * RR], g_tdl[MTOK * RR];

// ---------------- PTX helpers (all baseline sm_80+ features) ----------------
__device__ __forceinline__ uint32_t smem_u32(const void* p) {
    uint32_t a;
    asm("{ .reg .u64 t; cvta.to.shared.u64 t, %1; cvt.u32.u64 %0, t; }" : "=r"(a) : "l"(p));
    return a;
}
#define CPA(dst, src) \
    asm volatile("cp.async.cg.shared.global [%0], [%1], 16;\n" :: "r"(dst), "l"(src))
#define CPC() asm volatile("cp.async.commit_group;\n" ::: "memory")
#define CPW(n) asm volatile("cp.async.wait_group %0;\n" :: "n"(n) : "memory")
#define LDSM4(R, addr)                                                          \
    asm volatile("ldmatrix.sync.aligned.m8n8.x4.shared.b16 {%0,%1,%2,%3}, [%4];\n" \
        : "=r"((R)[0]), "=r"((R)[1]), "=r"((R)[2]), "=r"((R)[3]) : "r"(addr))
#define MMA16816(D, A, B0, B1)                                                  \
    asm volatile("mma.sync.aligned.m16n8k16.row.col.f32.bf16.bf16.f32 "         \
        "{%0,%1,%2,%3}, {%4,%5,%6,%7}, {%8,%9}, {%0,%1,%2,%3};\n"               \
        : "+f"((D)[0]), "+f"((D)[1]), "+f"((D)[2]), "+f"((D)[3])                \
        : "r"((A)[0]), "r"((A)[1]), "r"((A)[2]), "r"((A)[3]), "r"(B0), "r"(B1))

// SMEM layout per stage: A hi (10240) A lo (10240) B hi (20480) B lo (20480)
#define ASTRIDE 40
#define STG_BYTES 61440
#define A_OFF(h) ((h) * 10240)
#define B_OFF(h) (20480 + (h) * 20480)
#define GEMM_SMEM (2 * STG_BYTES)

// ---------------- fp32 -> bf16 hi/lo ----------------
__global__ __launch_bounds__(256)
void convert_hl(const float* __restrict__ s, size_t n,
                __nv_bfloat16* __restrict__ h, __nv_bfloat16* __restrict__ l)
{
    size_t i = ((size_t)blockIdx.x * 256 + threadIdx.x) * 4;
    if (i >= n) return;
    float4 v = *reinterpret_cast<const float4*>(s + i);
    float vv[4] = {v.x, v.y, v.z, v.w};
    __nv_bfloat16 hb[4], lb[4];
#pragma unroll
    for (int q = 0; q < 4; q++) {
        hb[q] = __float2bfloat16_rn(vv[q]);
        lb[q] = __float2bfloat16_rn(vv[q] - __bfloat162float(hb[q]));
    }
    *reinterpret_cast<uint2*>(h + i) = *reinterpret_cast<uint2*>(hb);
    *reinterpret_cast<uint2*>(l + i) = *reinterpret_cast<uint2*>(lb);
}

// ---------------- transpose fp32 [R,C] -> bf16 hi/lo [C,R] ----------------
__global__ __launch_bounds__(256)
void transpose_hl(const float* __restrict__ src, int R, int C,
                  __nv_bfloat16* __restrict__ dh, __nv_bfloat16* __restrict__ dl)
{
    __shared__ float t[32][33];
    int tx = threadIdx.x, ty = threadIdx.y;
    int x = blockIdx.x * 32 + tx, y0 = blockIdx.y * 32;
#pragma unroll
    for (int j = 0; j < 32; j += 8)
        t[ty + j][tx] = src[(size_t)(y0 + ty + j) * C + x];
    __syncthreads();
    int x2 = y0 + tx, y2 = blockIdx.x * 32;
#pragma unroll
    for (int j = 0; j < 32; j += 8) {
        float v = t[tx][ty + j];
        __nv_bfloat16 h = __float2bfloat16_rn(v);
        dh[(size_t)(y2 + ty + j) * R + x2] = h;
        dl[(size_t)(y2 + ty + j) * R + x2] = __float2bfloat16_rn(v - __bfloat162float(h));
    }
}

// ---------------- Lb [16,N] -> [N,16] hi/lo ----------------
__global__ __launch_bounds__(256)
void lb_transpose(const float* __restrict__ Lb, int N,
                  __nv_bfloat16* __restrict__ dh, __nv_bfloat16* __restrict__ dl)
{
    int n = blockIdx.x * 256 + threadIdx.x;
    if (n >= N) return;
#pragma unroll
    for (int r = 0; r < RR; r++) {
        float v = Lb[(size_t)r * N + n];
        __nv_bfloat16 h = __float2bfloat16_rn(v);
        dh[(size_t)n * RR + r] = h;
        dl[(size_t)n * RR + r] = __float2bfloat16_rn(v - __bfloat162float(h));
    }
}

// ---------------- LoRA-A: T = X @ A (SMEM-staged A), bf16 hi/lo out ----------------
__global__ __launch_bounds__(256)
void lora_a_kernel(const float* __restrict__ Xf,
                   const __nv_bfloat16* __restrict__ Xh, const __nv_bfloat16* __restrict__ Xl,
                   int K,
                   const float* __restrict__ A0, const float* __restrict__ A1,
                   __nv_bfloat16* __restrict__ T0h, __nv_bfloat16* __restrict__ T0l,
                   __nv_bfloat16* __restrict__ T1h, __nv_bfloat16* __restrict__ T1l)
{
    __shared__ float sA0[256 * 17], sA1[256 * 17];
    int tid = threadIdx.x, lane = tid & 31;
    int m = blockIdx.x * 8 + (tid >> 5);
    const bool dual = (A1 != nullptr);
    float a0[RR], a1[RR];
#pragma unroll
    for (int r = 0; r < RR; r++) { a0[r] = 0.f; a1[r] = 0.f; }

    for (int kt = 0; kt < K; kt += 256) {
        __syncthreads();
#pragma unroll
        for (int t = 0; t < 16; t++) {
            int i = tid + t * 256, row = i >> 4, r = i & 15;
            sA0[row * 17 + r] = A0[(size_t)(kt + row) * RR + r];
            if (dual) sA1[row * 17 + r] = A1[(size_t)(kt + row) * RR + r];
        }
        __syncthreads();
#pragma unroll
        for (int j = 0; j < 8; j++) {
            int k = j * 32 + lane;
            float x = Xf ? Xf[(size_t)m * K + kt + k]
                         : __bfloat162float(Xh[(size_t)m * K + kt + k]) +
                           __bfloat162float(Xl[(size_t)m * K + kt + k]);
#pragma unroll
            for (int r = 0; r < RR; r++) a0[r] += x * sA0[k * 17 + r];
            if (dual) {
#pragma unroll
                for (int r = 0; r < RR; r++) a1[r] += x * sA1[k * 17 + r];
            }
        }
    }
#pragma unroll
    for (int r = 0; r < RR; r++)
#pragma unroll
        for (int o = 16; o > 0; o >>= 1) {
            a0[r] += __shfl_xor_sync(~0u, a0[r], o);
            a1[r] += __shfl_xor_sync(~0u, a1[r], o);
        }
    if (lane == 0) {
#pragma unroll
        for (int r = 0; r < RR; r++) {
            __nv_bfloat16 h = __float2bfloat16_rn(a0[r]);
            T0h[(size_t)m * RR + r] = h;
            T0l[(size_t)m * RR + r] = __float2bfloat16_rn(a0[r] - __bfloat162float(h));
            if (dual) {
                __nv_bfloat16 h1 = __float2bfloat16_rn(a1[r]);
                T1h[(size_t)m * RR + r] = h1;
                T1l[(size_t)m * RR + r] = __float2bfloat16_rn(a1[r] - __bfloat162float(h1));
            }
        }
    }
}

// ---------------- HMMA GEMM: C = A@B^T + bias + T@L^T, hi/lo 3-combo ----------------
// A hi/lo [M,K]; B hi/lo [N,K]; T [M,16]; L [N,16].
// GATED: C := relu(GateY) * C, written as bf16 hi/lo (Xh/Xl); else fp32 Cf.
template <bool GATED>
__global__ __launch_bounds__(256, 1)
void gemm_mma(const __nv_bfloat16* __restrict__ Ah, const __nv_bfloat16* __restrict__ Al,
              const __nv_bfloat16* __restrict__ Bh, const __nv_bfloat16* __restrict__ Bl,
              const __nv_bfloat16* __restrict__ Th, const __nv_bfloat16* __restrict__ Tl,
              const __nv_bfloat16* __restrict__ Lh, const __nv_bfloat16* __restrict__ Ll,
              const float* __restrict__ bias,
              const float* __restrict__ GateY,
              float* __restrict__ Cf,
              __nv_bfloat16* __restrict__ Xh, __nv_bfloat16* __restrict__ Xl,
              int N, int K)
{
    extern __shared__ char dsm[];
    const uint32_t sb = smem_u32(dsm);
    const int tid = threadIdx.x, lane = tid & 31, wid = tid >> 5;
    const int wm = wid >> 2, wn = wid & 3;          // warp grid 2 x 4
    const int bm = blockIdx.y * 128, bn = blockIdx.x * 256;

    float acc[4][8][4];
#pragma unroll
    for (int a = 0; a < 4; a++)
#pragma unroll
        for (int b = 0; b < 8; b++)
#pragma unroll
            for (int c = 0; c < 4; c++) acc[a][b][c] = 0.f;

    auto load_stage = [&](int st, int k0) {
        uint32_t s0 = sb + st * STG_BYTES;
#pragma unroll
        for (int j = 0; j < 2; j++) {                 // A hi+lo: 512 chunks each half? (2 per thread)
            int c = tid + j * 256;
            int row = c >> 2, cg = (c & 3) * 8;
            uint32_t d = (uint32_t)(row * ASTRIDE + cg) * 2;
            CPA(s0 + A_OFF(0) + d, Ah + (size_t)(bm + row) * K + k0 + cg);
            CPA(s0 + A_OFF(1) + d, Al + (size_t)(bm + row) * K + k0 + cg);
        }
#pragma unroll
        for (int j = 0; j < 4; j++) {                 // B hi+lo: 256 rows
            int c = tid + j * 256;
            int row = c >> 2, cg = (c & 3) * 8;
            uint32_t d = (uint32_t)(row * ASTRIDE + cg) * 2;
            CPA(s0 + B_OFF(0) + d, Bh + (size_t)(bn + row) * K + k0 + cg);
            CPA(s0 + B_OFF(1) + d, Bl + (size_t)(bn + row) * K + k0 + cg);
        }
    };

    auto compute_ks = [&](uint32_t s0, int kbase) {
        const int ar = lane & 15;
        const int kc = kbase + (lane >> 4) * 8;
        uint32_t ah[4][4], al[4][4], bb[4][4];
#pragma unroll
        for (int mi = 0; mi < 4; mi++)
            LDSM4(ah[mi], s0 + A_OFF(0) + (uint32_t)((wm * 64 + mi * 16 + ar) * ASTRIDE + kc) * 2);
#pragma unroll
        for (int p = 0; p < 4; p++)
            LDSM4(bb[p], s0 + B_OFF(0) + (uint32_t)((wn * 64 + p * 16 + ar) * ASTRIDE + kc) * 2);
#pragma unroll
        for (int mi = 0; mi < 4; mi++)                // hh
#pragma unroll
            for (int ni = 0; ni < 8; ni++)
                MMA16816(acc[mi][ni], ah[mi], bb[ni >> 1][ni & 1], bb[ni >> 1][(ni & 1) + 2]);
#pragma unroll
        for (int mi = 0; mi < 4; mi++)
            LDSM4(al[mi], s0 + A_OFF(1) + (uint32_t)((wm * 64 + mi * 16 + ar) * ASTRIDE + kc) * 2);
#pragma unroll
        for (int mi = 0; mi < 4; mi++)                // lh
#pragma unroll
            for (int ni = 0; ni < 8; ni++)
                MMA16816(acc[mi][ni], al[mi], bb[ni >> 1][ni & 1], bb[ni >> 1][(ni & 1) + 2]);
#pragma unroll
        for (int p = 0; p < 4; p++)
            LDSM4(bb[p], s0 + B_OFF(1) + (uint32_t)((wn * 64 + p * 16 + ar) * ASTRIDE + kc) * 2);
#pragma unroll
        for (int mi = 0; mi < 4; mi++)                // hl
#pragma unroll
            for (int ni = 0; ni < 8; ni++)
                MMA16816(acc[mi][ni], ah[mi], bb[ni >> 1][ni & 1], bb[ni >> 1][(ni & 1) + 2]);
    };

    const int KC = K / 32;
    load_stage(0, 0); CPC();
    if (KC > 1) { load_stage(1, 32); CPC(); }

    for (int c = 0; c < KC; c++) {
        if (c + 1 < KC) { CPW(1); } else { CPW(0); }
        __syncthreads();
        uint32_t s0 = sb + (uint32_t)(c & 1) * STG_BYTES;
        compute_ks(s0, 0);
        compute_ks(s0, 16);
        __syncthreads();
        if (c + 2 < KC) { load_stage(c & 1, (c + 2) * 32); CPC(); }
    }

    // ---- LoRA k16 chunk into stage 0 ----
    {
        int row = tid >> 1, cg = (tid & 1) * 8;
        uint32_t d = (uint32_t)(row * ASTRIDE + cg) * 2;
        *(uint4*)(dsm + A_OFF(0) + d) = *(const uint4*)(Th + (size_t)(bm + row) * RR + cg);
        *(uint4*)(dsm + A_OFF(1) + d) = *(const uint4*)(Tl + (size_t)(bm + row) * RR + cg);
#pragma unroll
        for (int j = 0; j < 2; j++) {
            int c = tid + j * 256;
            int brow = c >> 1, bcg = (c & 1) * 8;
            uint32_t bd = (uint32_t)(brow * ASTRIDE + bcg) * 2;
            *(uint4*)(dsm + B_OFF(0) + bd) = *(const uint4*)(Lh + (size_t)(bn + brow) * RR + bcg);
            *(uint4*)(dsm + B_OFF(1) + bd) = *(const uint4*)(Ll + (size_t)(bn + brow) * RR + bcg);
        }
        __syncthreads();
        compute_ks(sb, 0);
    }

    // ---- epilogue ----
#pragma unroll
    for (int mi = 0; mi < 4; mi++) {
        int r0 = bm + wm * 64 + mi * 16 + (lane >> 2);
#pragma unroll
        for (int ni = 0; ni < 8; ni++) {
            int col = bn + wn * 64 + ni * 8 + (lane & 3) * 2;
            float bs0 = bias[col], bs1 = bias[col + 1];
#pragma unroll
            for (int h2 = 0; h2 < 2; h2++) {
                int r = r0 + h2 * 8;
                float v0 = acc[mi][ni][h2 * 2 + 0] + bs0;
                float v1 = acc[mi][ni][h2 * 2 + 1] + bs1;
                size_t off = (size_t)r * N + col;
                if (GATED) {
                    float2 g = *(const float2*)(GateY + off);
                    v0 *= fmaxf(g.x, 0.f);
                    v1 *= fmaxf(g.y, 0.f);
                    __nv_bfloat16 h0 = __float2bfloat16_rn(v0);
                    __nv_bfloat16 h1 = __float2bfloat16_rn(v1);
                    __nv_bfloat16 l0 = __float2bfloat16_rn(v0 - __bfloat162float(h0));
                    __nv_bfloat16 l1 = __float2bfloat16_rn(v1 - __bfloat162float(h1));
                    *(__nv_bfloat162*)(Xh + off) = __halves2bfloat162(h0, h1);
                    *(__nv_bfloat162*)(Xl + off) = __halves2bfloat162(l0, l1);
                } else {
                    *(float2*)(Cf + off) = make_float2(v0, v1);
                }
            }
        }
    }
}

// ---------------- launcher ----------------
extern "C" void kernel_launch(void* const* d_in, const int* in_sizes, int n_in,
                              void* d_out, int out_size)
{
    const float* x1     = (const float*)d_in[0];
    const float* w_gate = (const float*)d_in[1];
    const float* b_gate = (const float*)d_in[2];
    const float* wga    = (const float*)d_in[3];
    const float* wgb    = (const float*)d_in[4];
    const float* w_up   = (const float*)d_in[5];
    const float* b_up   = (const float*)d_in[6];
    const float* wua    = (const float*)d_in[7];
    const float* wub    = (const float*)d_in[8];
    const float* w_down = (const float*)d_in[9];
    const float* b_down = (const float*)d_in[10];
    const float* wda    = (const float*)d_in[11];
    const float* wdb    = (const float*)d_in[12];
    float* out = (float*)d_out;

#define SYM(p, s) void* p; cudaGetSymbolAddress(&p, s)
    SYM(y1, g_y1);
    SYM(x1h, g_x1h); SYM(x1l, g_x1l); SYM(x3h, g_x3h); SYM(x3l, g_x3l);
    SYM(wgh, g_wgh); SYM(wgl, g_wgl); SYM(wuh, g_wuh); SYM(wul, g_wul);
    SYM(wdh, g_wdh); SYM(wdl, g_wdl);
    SYM(lgh, g_lgh); SYM(lgl, g_lgl); SYM(luh, g_luh); SYM(lul, g_lul);
    SYM(ldh, g_ldh); SYM(ldl, g_ldl);
    SYM(tgh, g_tgh); SYM(tgl, g_tgl); SYM(tuh, g_tuh); SYM(tul, g_tul);
    SYM(tdh, g_tdh); SYM(tdl, g_tdl);
#undef SYM
#define BF(p) ((__nv_bfloat16*)(p))

    cudaFuncSetAttribute(gemm_mma<false>, cudaFuncAttributeMaxDynamicSharedMemorySize, GEMM_SMEM);
    cudaFuncSetAttribute(gemm_mma<true>,  cudaFuncAttributeMaxDynamicSharedMemorySize, GEMM_SMEM);

    // conversions / transposes
    convert_hl<<<(int)((size_t)MTOK * DDIM / 1024), 256>>>(x1, (size_t)MTOK * DDIM, BF(x1h), BF(x1l));
    transpose_hl<<<dim3(FDIM / 32, DDIM / 32), dim3(32, 8)>>>(w_gate, DDIM, FDIM, BF(wgh), BF(wgl));
    transpose_hl<<<dim3(FDIM / 32, DDIM / 32), dim3(32, 8)>>>(w_up,   DDIM, FDIM, BF(wuh), BF(wul));
    transpose_hl<<<dim3(DDIM / 32, FDIM / 32), dim3(32, 8)>>>(w_down, FDIM, DDIM, BF(wdh), BF(wdl));
    lb_transpose<<<FDIM / 256, 256>>>(wgb, FDIM, BF(lgh), BF(lgl));
    lb_transpose<<<FDIM / 256, 256>>>(wub, FDIM, BF(luh), BF(lul));
    lb_transpose<<<DDIM / 256, 256>>>(wdb, DDIM, BF(ldh), BF(ldl));

    // LoRA-A for gate + up
    lora_a_kernel<<<MTOK / 8, 256>>>(x1, nullptr, nullptr, DDIM, wga, wua,
                                     BF(tgh), BF(tgl), BF(tuh), BF(tul));

    // gate GEMM -> y1 (fp32, bias + LoRA folded)
    gemm_mma<false><<<dim3(FDIM / 256, MTOK / 128), 256, GEMM_SMEM>>>(
        BF(x1h), BF(x1l), BF(wgh), BF(wgl), BF(tgh), BF(tgl), BF(lgh), BF(lgl),
        b_gate, nullptr, (float*)y1, nullptr, nullptr, FDIM, DDIM);

    // up GEMM, gated epilogue -> x3 bf16 hi/lo
    gemm_mma<true><<<dim3(FDIM / 256, MTOK / 128), 256, GEMM_SMEM>>>(
        BF(x1h), BF(x1l), BF(wuh), BF(wul), BF(tuh), BF(tul), BF(luh), BF(lul),
        b_up, (const float*)y1, nullptr, BF(x3h), BF(x3l), FDIM, DDIM);

    // LoRA-A for down (reads x3 hi/lo)
    lora_a_kernel<<<MTOK / 8, 256>>>(nullptr, BF(x3h), BF(x3l), FDIM, wda, nullptr,
                                     BF(tdh), BF(tdl), nullptr, nullptr);

    // down GEMM -> out (fp32)
    gemm_mma<false><<<dim3(DDIM / 256, MTOK / 128), 256, GEMM_SMEM>>>(
        BF(x3h), BF(x3l), BF(wdh), BF(wdl), BF(tdh), BF(tdl), BF(ldh), BF(ldl),
        b_down, nullptr, out, nullptr, nullptr, DDIM, FDIM);
}

// round 6
// speedup vs baseline: 2.0697x; 1.0327x over previous
#include <cuda_runtime.h>
#include <cuda_bf16.h>
#include <cstdint>

#define MTOK 8192
#define DDIM 2048
#define FDIM 8192
#define RR   16

// ---------------- device scratch (allocation-free) ----------------
__device__ __align__(1024) __nv_bfloat16 g_x1h[(size_t)MTOK * DDIM];
__device__ __align__(1024) __nv_bfloat16 g_x1l[(size_t)MTOK * DDIM];
__device__ __align__(1024) __nv_bfloat16 g_x3h[(size_t)MTOK * FDIM];
__device__ __align__(1024) __nv_bfloat16 g_x3l[(size_t)MTOK * FDIM];
__device__ __align__(1024) __nv_bfloat16 g_wgh[(size_t)FDIM * DDIM];
__device__ __align__(1024) __nv_bfloat16 g_wgl[(size_t)FDIM * DDIM];
__device__ __align__(1024) __nv_bfloat16 g_wuh[(size_t)FDIM * DDIM];
__device__ __align__(1024) __nv_bfloat16 g_wul[(size_t)FDIM * DDIM];
__device__ __align__(1024) __nv_bfloat16 g_wdh[(size_t)DDIM * FDIM];
__device__ __align__(1024) __nv_bfloat16 g_wdl[(size_t)DDIM * FDIM];
__device__ __align__(1024) __nv_bfloat16 g_lgh[FDIM * RR], g_lgl[FDIM * RR];
__device__ __align__(1024) __nv_bfloat16 g_luh[FDIM * RR], g_lul[FDIM * RR];
__device__ __align__(1024) __nv_bfloat16 g_ldh[DDIM * RR], g_ldl[DDIM * RR];
__device__ __align__(1024) __nv_bfloat16 g_tgh[MTOK * RR], g_tgl[MTOK * RR];
__device__ __align__(1024) __nv_bfloat16 g_tuh[MTOK * RR], g_tul[MTOK * RR];
__device__ __align__(1024) __nv_bfloat16 g_tdh[MTOK * RR], g_tdl[MTOK * RR];

// ---------------- PTX helpers ----------------
__device__ __forceinline__ uint32_t smem_u32(const void* p) {
    uint32_t a;
    asm("{ .reg .u64 t; cvta.to.shared.u64 t, %1; cvt.u32.u64 %0, t; }" : "=r"(a) : "l"(p));
    return a;
}
#define CPA(dst, src) \
    asm volatile("cp.async.cg.shared.global [%0], [%1], 16;\n" :: "r"(dst), "l"(src))
#define CPC() asm volatile("cp.async.commit_group;\n" ::: "memory")
#define CPW(n) asm volatile("cp.async.wait_group %0;\n" :: "n"(n) : "memory")
#define LDSM4(R, addr)                                                          \
    asm volatile("ldmatrix.sync.aligned.m8n8.x4.shared.b16 {%0,%1,%2,%3}, [%4];\n" \
        : "=r"((R)[0]), "=r"((R)[1]), "=r"((R)[2]), "=r"((R)[3]) : "r"(addr))
#define MMA16816(D, A, B0, B1)                                                  \
    asm volatile("mma.sync.aligned.m16n8k16.row.col.f32.bf16.bf16.f32 "         \
        "{%0,%1,%2,%3}, {%4,%5,%6,%7}, {%8,%9}, {%0,%1,%2,%3};\n"               \
        : "+f"((D)[0]), "+f"((D)[1]), "+f"((D)[2]), "+f"((D)[3])                \
        : "r"((A)[0]), "r"((A)[1]), "r"((A)[2]), "r"((A)[3]), "r"(B0), "r"(B1))

// SMEM per stage: Ah(10240) Al(10240) Bh(20480) Bl(20480) = 61440; 3 stages
#define ASTRIDE 40
#define STG_BYTES 61440
#define A_OFF(h) ((h) * 10240)
#define B_OFF(h) (20480 + (h) * 20480)
#define GEMM_SMEM (3 * STG_BYTES)

// ---------------- fp32 -> bf16 hi/lo ----------------
__global__ __launch_bounds__(256)
void convert_hl(const float* __restrict__ s, size_t n,
                __nv_bfloat16* __restrict__ h, __nv_bfloat16* __restrict__ l)
{
    size_t i = ((size_t)blockIdx.x * 256 + threadIdx.x) * 4;
    if (i >= n) return;
    float4 v = *reinterpret_cast<const float4*>(s + i);
    float vv[4] = {v.x, v.y, v.z, v.w};
    __nv_bfloat16 hb[4], lb[4];
#pragma unroll
    for (int q = 0; q < 4; q++) {
        hb[q] = __float2bfloat16_rn(vv[q]);
        lb[q] = __float2bfloat16_rn(vv[q] - __bfloat162float(hb[q]));
    }
    *reinterpret_cast<uint2*>(h + i) = *reinterpret_cast<uint2*>(hb);
    *reinterpret_cast<uint2*>(l + i) = *reinterpret_cast<uint2*>(lb);
}

// ---------------- transpose fp32 [R,C] -> bf16 hi/lo [C,R] ----------------
__global__ __launch_bounds__(256)
void transpose_hl(const float* __restrict__ src, int R, int C,
                  __nv_bfloat16* __restrict__ dh, __nv_bfloat16* __restrict__ dl)
{
    __shared__ float t[32][33];
    int tx = threadIdx.x, ty = threadIdx.y;
    int x = blockIdx.x * 32 + tx, y0 = blockIdx.y * 32;
#pragma unroll
    for (int j = 0; j < 32; j += 8)
        t[ty + j][tx] = src[(size_t)(y0 + ty + j) * C + x];
    __syncthreads();
    int x2 = y0 + tx, y2 = blockIdx.x * 32;
#pragma unroll
    for (int j = 0; j < 32; j += 8) {
        float v = t[tx][ty + j];
        __nv_bfloat16 h = __float2bfloat16_rn(v);
        dh[(size_t)(y2 + ty + j) * R + x2] = h;
        dl[(size_t)(y2 + ty + j) * R + x2] = __float2bfloat16_rn(v - __bfloat162float(h));
    }
}

// ---------------- Lb [16,N] -> [N,16] hi/lo ----------------
__global__ __launch_bounds__(256)
void lb_transpose(const float* __restrict__ Lb, int N,
                  __nv_bfloat16* __restrict__ dh, __nv_bfloat16* __restrict__ dl)
{
    int n = blockIdx.x * 256 + threadIdx.x;
    if (n >= N) return;
#pragma unroll
    for (int r = 0; r < RR; r++) {
        float v = Lb[(size_t)r * N + n];
        __nv_bfloat16 h = __float2bfloat16_rn(v);
        dh[(size_t)n * RR + r] = h;
        dl[(size_t)n * RR + r] = __float2bfloat16_rn(v - __bfloat162float(h));
    }
}

// ---------------- LoRA-A: T = X @ A, bf16 hi/lo out ----------------
__global__ __launch_bounds__(256)
void lora_a_kernel(const float* __restrict__ Xf,
                   const __nv_bfloat16* __restrict__ Xh, const __nv_bfloat16* __restrict__ Xl,
                   int K,
                   const float* __restrict__ A0, const float* __restrict__ A1,
                   __nv_bfloat16* __restrict__ T0h, __nv_bfloat16* __restrict__ T0l,
                   __nv_bfloat16* __restrict__ T1h, __nv_bfloat16* __restrict__ T1l)
{
    __shared__ float sA0[256 * 17], sA1[256 * 17];
    int tid = threadIdx.x, lane = tid & 31;
    int m = blockIdx.x * 8 + (tid >> 5);
    const bool dual = (A1 != nullptr);
    float a0[RR], a1[RR];
#pragma unroll
    for (int r = 0; r < RR; r++) { a0[r] = 0.f; a1[r] = 0.f; }

    for (int kt = 0; kt < K; kt += 256) {
        __syncthreads();
#pragma unroll
        for (int t = 0; t < 16; t++) {
            int i = tid + t * 256, row = i >> 4, r = i & 15;
            sA0[row * 17 + r] = A0[(size_t)(kt + row) * RR + r];
            if (dual) sA1[row * 17 + r] = A1[(size_t)(kt + row) * RR + r];
        }
        __syncthreads();
#pragma unroll
        for (int j = 0; j < 8; j++) {
            int k = j * 32 + lane;
            float x = Xf ? Xf[(size_t)m * K + kt + k]
                         : __bfloat162float(Xh[(size_t)m * K + kt + k]) +
                           __bfloat162float(Xl[(size_t)m * K + kt + k]);
#pragma unroll
            for (int r = 0; r < RR; r++) a0[r] += x * sA0[k * 17 + r];
            if (dual) {
#pragma unroll
                for (int r = 0; r < RR; r++) a1[r] += x * sA1[k * 17 + r];
            }
        }
    }
#pragma unroll
    for (int r = 0; r < RR; r++)
#pragma unroll
        for (int o = 16; o > 0; o >>= 1) {
            a0[r] += __shfl_xor_sync(~0u, a0[r], o);
            a1[r] += __shfl_xor_sync(~0u, a1[r], o);
        }
    if (lane == 0) {
#pragma unroll
        for (int r = 0; r < RR; r++) {
            __nv_bfloat16 h = __float2bfloat16_rn(a0[r]);
            T0h[(size_t)m * RR + r] = h;
            T0l[(size_t)m * RR + r] = __float2bfloat16_rn(a0[r] - __bfloat162float(h));
            if (dual) {
                __nv_bfloat16 h1 = __float2bfloat16_rn(a1[r]);
                T1h[(size_t)m * RR + r] = h1;
                T1l[(size_t)m * RR + r] = __float2bfloat16_rn(a1[r] - __bfloat162float(h1));
            }
        }
    }
}

// ---------------- unified HMMA GEMM ----------------
// B region rows 0..127 = weight0 tile, 128..255 = weight1 tile.
// MODE 0 (down): weight0/1 = same W, cols [bn,bn+128)/[bn+128,bn+256); T0=T1=t_down.
// MODE 1 (fused gate+up): weight0 = Wg (T0=t_gate), weight1 = Wu (T1=t_up);
//                         output x3 = relu(y_g)*y_u as bf16 hi/lo.
template <int MODE>
__global__ __launch_bounds__(256, 1)
void gemm_mma(const __nv_bfloat16* __restrict__ Ah, const __nv_bfloat16* __restrict__ Al,
              const __nv_bfloat16* __restrict__ B0h, const __nv_bfloat16* __restrict__ B0l,
              const __nv_bfloat16* __restrict__ B1h, const __nv_bfloat16* __restrict__ B1l,
              const __nv_bfloat16* __restrict__ T0h, const __nv_bfloat16* __restrict__ T0l,
              const __nv_bfloat16* __restrict__ T1h, const __nv_bfloat16* __restrict__ T1l,
              const __nv_bfloat16* __restrict__ L0h, const __nv_bfloat16* __restrict__ L0l,
              const __nv_bfloat16* __restrict__ L1h, const __nv_bfloat16* __restrict__ L1l,
              const float* __restrict__ bias0, const float* __restrict__ bias1,
              float* __restrict__ Cf,
              __nv_bfloat16* __restrict__ Xh, __nv_bfloat16* __restrict__ Xl,
              int N, int K)
{
    extern __shared__ char dsm[];
    const uint32_t sb = smem_u32(dsm);
    const int tid = threadIdx.x, lane = tid & 31, wid = tid >> 5;
    const int wm = wid >> 2, wn = wid & 3;            // 2 x 4 warps
    const int bm = blockIdx.y * 128;
    const int bn = blockIdx.x * (MODE == 0 ? 256 : 128);

    float acc[2][4][4][4];
#pragma unroll
    for (int o = 0; o < 2; o++)
#pragma unroll
        for (int a = 0; a < 4; a++)
#pragma unroll
            for (int b = 0; b < 4; b++)
#pragma unroll
                for (int c = 0; c < 4; c++) acc[o][a][b][c] = 0.f;

    auto load_stage = [&](int st, int k0) {
        uint32_t s0 = sb + (uint32_t)st * STG_BYTES;
#pragma unroll
        for (int j = 0; j < 2; j++) {                 // A: 128 rows x 64B
            int c = tid + j * 256;
            int row = c >> 2, cg = (c & 3) * 8;
            uint32_t d = (uint32_t)(row * ASTRIDE + cg) * 2;
            CPA(s0 + A_OFF(0) + d, Ah + (size_t)(bm + row) * K + k0 + cg);
            CPA(s0 + A_OFF(1) + d, Al + (size_t)(bm + row) * K + k0 + cg);
        }
#pragma unroll
        for (int j = 0; j < 4; j++) {                 // B: 256 rows x 64B
            int c = tid + j * 256;
            int row = c >> 2, cg = (c & 3) * 8;
            int rr = (MODE == 0) ? row : (row & 127);
            const __nv_bfloat16* ph = (row < 128) ? B0h : B1h;
            const __nv_bfloat16* pl = (row < 128) ? B0l : B1l;
            uint32_t d = (uint32_t)(row * ASTRIDE + cg) * 2;
            CPA(s0 + B_OFF(0) + d, ph + (size_t)(bn + rr) * K + k0 + cg);
            CPA(s0 + B_OFF(1) + d, pl + (size_t)(bn + rr) * K + k0 + cg);
        }
    };

    const int ar = lane & 15;
    const int koff = (lane >> 4) * 8;

    auto compute_ks = [&](uint32_t s0, int kbase) {
        const int kc = kbase + koff;
        uint32_t ah[4][4], al[4][4], b0[2][4], b1[2][4];
#pragma unroll
        for (int mi = 0; mi < 4; mi++)
            LDSM4(ah[mi], s0 + A_OFF(0) + (uint32_t)((wm * 64 + mi * 16 + ar) * ASTRIDE + kc) * 2);
#pragma unroll
        for (int nb = 0; nb < 2; nb++) {
            LDSM4(b0[nb], s0 + B_OFF(0) + (uint32_t)((wn * 32 + nb * 16 + ar) * ASTRIDE + kc) * 2);
            LDSM4(b1[nb], s0 + B_OFF(0) + (uint32_t)((128 + wn * 32 + nb * 16 + ar) * ASTRIDE + kc) * 2);
        }
#pragma unroll
        for (int mi = 0; mi < 4; mi++)
#pragma unroll
            for (int ni = 0; ni < 4; ni++) {
                MMA16816(acc[0][mi][ni], ah[mi], b0[ni >> 1][ni & 1], b0[ni >> 1][(ni & 1) + 2]);
                MMA16816(acc[1][mi][ni], ah[mi], b1[ni >> 1][ni & 1], b1[ni >> 1][(ni & 1) + 2]);
            }
#pragma unroll
        for (int mi = 0; mi < 4; mi++)
            LDSM4(al[mi], s0 + A_OFF(1) + (uint32_t)((wm * 64 + mi * 16 + ar) * ASTRIDE + kc) * 2);
#pragma unroll
        for (int mi = 0; mi < 4; mi++)
#pragma unroll
            for (int ni = 0; ni < 4; ni++) {
                MMA16816(acc[0][mi][ni], al[mi], b0[ni >> 1][ni & 1], b0[ni >> 1][(ni & 1) + 2]);
                MMA16816(acc[1][mi][ni], al[mi], b1[ni >> 1][ni & 1], b1[ni >> 1][(ni & 1) + 2]);
            }
#pragma unroll
        for (int nb = 0; nb < 2; nb++) {
            LDSM4(b0[nb], s0 + B_OFF(1) + (uint32_t)((wn * 32 + nb * 16 + ar) * ASTRIDE + kc) * 2);
            LDSM4(b1[nb], s0 + B_OFF(1) + (uint32_t)((128 + wn * 32 + nb * 16 + ar) * ASTRIDE + kc) * 2);
        }
#pragma unroll
        for (int mi = 0; mi < 4; mi++)
#pragma unroll
            for (int ni = 0; ni < 4; ni++) {
                MMA16816(acc[0][mi][ni], ah[mi], b0[ni >> 1][ni & 1], b0[ni >> 1][(ni & 1) + 2]);
                MMA16816(acc[1][mi][ni], ah[mi], b1[ni >> 1][ni & 1], b1[ni >> 1][(ni & 1) + 2]);
            }
    };

    const int KC = K / 32;
    load_stage(0, 0); CPC();
    load_stage(1, 32); CPC();

    for (int c = 0; c < KC; c++) {
        if (c + 1 < KC) { CPW(1); } else { CPW(0); }
        __syncthreads();
        if (c + 2 < KC) { load_stage((c + 2) % 3, (c + 2) * 32); CPC(); }
        uint32_t s0 = sb + (uint32_t)(c % 3) * STG_BYTES;
        compute_ks(s0, 0);
        compute_ks(s0, 16);
    }

    // ---- LoRA k16 chunk: T0 in stage0 A region, T1 in stage1 A region ----
    __syncthreads();
    {
        int row = tid >> 1, cg = (tid & 1) * 8;       // 128 rows x 32B
        uint32_t d = (uint32_t)(row * ASTRIDE + cg) * 2;
        *(uint4*)(dsm + A_OFF(0) + d) = *(const uint4*)(T0h + (size_t)(bm + row) * RR + cg);
        *(uint4*)(dsm + A_OFF(1) + d) = *(const uint4*)(T0l + (size_t)(bm + row) * RR + cg);
        *(uint4*)(dsm + STG_BYTES + A_OFF(0) + d) = *(const uint4*)(T1h + (size_t)(bm + row) * RR + cg);
        *(uint4*)(dsm + STG_BYTES + A_OFF(1) + d) = *(const uint4*)(T1l + (size_t)(bm + row) * RR + cg);
#pragma unroll
        for (int j = 0; j < 2; j++) {                 // L: 256 rows x 32B
            int c = tid + j * 256;
            int brow = c >> 1, bcg = (c & 1) * 8;
            int rr = (MODE == 0) ? brow : (brow & 127);
            const __nv_bfloat16* ph = (brow < 128) ? L0h : L1h;
            const __nv_bfloat16* pl = (brow < 128) ? L0l : L1l;
            uint32_t bd = (uint32_t)(brow * ASTRIDE + bcg) * 2;
            *(uint4*)(dsm + B_OFF(0) + bd) = *(const uint4*)(ph + (size_t)(bn + rr) * RR + bcg);
            *(uint4*)(dsm + B_OFF(1) + bd) = *(const uint4*)(pl + (size_t)(bn + rr) * RR + bcg);
        }
        __syncthreads();
        // per-output LoRA MMA: output o uses T_o (A from stage o) x L_o (B rows o*128..)
#pragma unroll
        for (int o = 0; o < 2; o++) {
            uint32_t sA = sb + (uint32_t)o * STG_BYTES;
            uint32_t ah[4][4], al[4][4], bb[2][4];
#pragma unroll
            for (int mi = 0; mi < 4; mi++) {
                LDSM4(ah[mi], sA + A_OFF(0) + (uint32_t)((wm * 64 + mi * 16 + ar) * ASTRIDE + koff) * 2);
                LDSM4(al[mi], sA + A_OFF(1) + (uint32_t)((wm * 64 + mi * 16 + ar) * ASTRIDE + koff) * 2);
            }
#pragma unroll
            for (int nb = 0; nb < 2; nb++)
                LDSM4(bb[nb], sb + B_OFF(0) + (uint32_t)((o * 128 + wn * 32 + nb * 16 + ar) * ASTRIDE + koff) * 2);
#pragma unroll
            for (int mi = 0; mi < 4; mi++)
#pragma unroll
                for (int ni = 0; ni < 4; ni++) {
                    MMA16816(acc[o][mi][ni], ah[mi], bb[ni >> 1][ni & 1], bb[ni >> 1][(ni & 1) + 2]);
                    MMA16816(acc[o][mi][ni], al[mi], bb[ni >> 1][ni & 1], bb[ni >> 1][(ni & 1) + 2]);
                }
#pragma unroll
            for (int nb = 0; nb < 2; nb++)
                LDSM4(bb[nb], sb + B_OFF(1) + (uint32_t)((o * 128 + wn * 32 + nb * 16 + ar) * ASTRIDE + koff) * 2);
#pragma unroll
            for (int mi = 0; mi < 4; mi++)
#pragma unroll
                for (int ni = 0; ni < 4; ni++)
                    MMA16816(acc[o][mi][ni], ah[mi], bb[ni >> 1][ni & 1], bb[ni >> 1][(ni & 1) + 2]);
        }
    }

    // ---- epilogue ----
#pragma unroll
    for (int mi = 0; mi < 4; mi++) {
        int r0 = bm + wm * 64 + mi * 16 + (lane >> 2);
#pragma unroll
        for (int ni = 0; ni < 4; ni++) {
            int cl = wn * 32 + ni * 8 + (lane & 3) * 2;
            if (MODE == 1) {
                float bg0 = bias0[bn + cl], bg1 = bias0[bn + cl + 1];
                float bu0 = bias1[bn + cl], bu1 = bias1[bn + cl + 1];
#pragma unroll
                for (int h2 = 0; h2 < 2; h2++) {
                    int r = r0 + h2 * 8;
                    float g0 = acc[0][mi][ni][h2 * 2 + 0] + bg0;
                    float g1 = acc[0][mi][ni][h2 * 2 + 1] + bg1;
                    float u0 = acc[1][mi][ni][h2 * 2 + 0] + bu0;
                    float u1 = acc[1][mi][ni][h2 * 2 + 1] + bu1;
                    float v0 = fmaxf(g0, 0.f) * u0;
                    float v1 = fmaxf(g1, 0.f) * u1;
                    __nv_bfloat16 h0 = __float2bfloat16_rn(v0);
                    __nv_bfloat16 h1 = __float2bfloat16_rn(v1);
                    __nv_bfloat16 l0 = __float2bfloat16_rn(v0 - __bfloat162float(h0));
                    __nv_bfloat16 l1 = __float2bfloat16_rn(v1 - __bfloat162float(h1));
                    size_t off = (size_t)r * N + bn + cl;
                    *(__nv_bfloat162*)(Xh + off) = __halves2bfloat162(h0, h1);
                    *(__nv_bfloat162*)(Xl + off) = __halves2bfloat162(l0, l1);
                }
            } else {
#pragma unroll
                for (int o = 0; o < 2; o++) {
                    int col = bn + o * 128 + cl;
                    float b0 = bias0[col], b1 = bias0[col + 1];
#pragma unroll
                    for (int h2 = 0; h2 < 2; h2++) {
                        int r = r0 + h2 * 8;
                        size_t off = (size_t)r * N + col;
                        *(float2*)(Cf + off) = make_float2(
                            acc[o][mi][ni][h2 * 2 + 0] + b0,
                            acc[o][mi][ni][h2 * 2 + 1] + b1);
                    }
                }
            }
        }
    }
}

// ---------------- launcher ----------------
extern "C" void kernel_launch(void* const* d_in, const int* in_sizes, int n_in,
                              void* d_out, int out_size)
{
    const float* x1     = (const float*)d_in[0];
    const float* w_gate = (const float*)d_in[1];
    const float* b_gate = (const float*)d_in[2];
    const float* wga    = (const float*)d_in[3];
    const float* wgb    = (const float*)d_in[4];
    const float* w_up   = (const float*)d_in[5];
    const float* b_up   = (const float*)d_in[6];
    const float* wua    = (const float*)d_in[7];
    const float* wub    = (const float*)d_in[8];
    const float* w_down = (const float*)d_in[9];
    const float* b_down = (const float*)d_in[10];
    const float* wda    = (const float*)d_in[11];
    const float* wdb    = (const float*)d_in[12];
    float* out = (float*)d_out;

#define SYM(p, s) void* p; cudaGetSymbolAddress(&p, s)
    SYM(x1h, g_x1h); SYM(x1l, g_x1l); SYM(x3h, g_x3h); SYM(x3l, g_x3l);
    SYM(wgh, g_wgh); SYM(wgl, g_wgl); SYM(wuh, g_wuh); SYM(wul, g_wul);
    SYM(wdh, g_wdh); SYM(wdl, g_wdl);
    SYM(lgh, g_lgh); SYM(lgl, g_lgl); SYM(luh, g_luh); SYM(lul, g_lul);
    SYM(ldh, g_ldh); SYM(ldl, g_ldl);
    SYM(tgh, g_tgh); SYM(tgl, g_tgl); SYM(tuh, g_tuh); SYM(tul, g_tul);
    SYM(tdh, g_tdh); SYM(tdl, g_tdl);
#undef SYM
#define BF(p) ((__nv_bfloat16*)(p))

    cudaFuncSetAttribute(gemm_mma<0>, cudaFuncAttributeMaxDynamicSharedMemorySize, GEMM_SMEM);
    cudaFuncSetAttribute(gemm_mma<1>, cudaFuncAttributeMaxDynamicSharedMemorySize, GEMM_SMEM);

    // conversions / transposes
    convert_hl<<<(int)((size_t)MTOK * DDIM / 1024), 256>>>(x1, (size_t)MTOK * DDIM, BF(x1h), BF(x1l));
    transpose_hl<<<dim3(FDIM / 32, DDIM / 32), dim3(32, 8)>>>(w_gate, DDIM, FDIM, BF(wgh), BF(wgl));
    transpose_hl<<<dim3(FDIM / 32, DDIM / 32), dim3(32, 8)>>>(w_up,   DDIM, FDIM, BF(wuh), BF(wul));
    transpose_hl<<<dim3(DDIM / 32, FDIM / 32), dim3(32, 8)>>>(w_down, FDIM, DDIM, BF(wdh), BF(wdl));
    lb_transpose<<<FDIM / 256, 256>>>(wgb, FDIM, BF(lgh), BF(lgl));
    lb_transpose<<<FDIM / 256, 256>>>(wub, FDIM, BF(luh), BF(lul));
    lb_transpose<<<DDIM / 256, 256>>>(wdb, DDIM, BF(ldh), BF(ldl));

    // LoRA-A for gate + up
    lora_a_kernel<<<MTOK / 8, 256>>>(x1, nullptr, nullptr, DDIM, wga, wua,
                                     BF(tgh), BF(tgl), BF(tuh), BF(tul));

    // fused gate+up -> x3 bf16 hi/lo
    gemm_mma<1><<<dim3(FDIM / 128, MTOK / 128), 256, GEMM_SMEM>>>(
        BF(x1h), BF(x1l),
        BF(wgh), BF(wgl), BF(wuh), BF(wul),
        BF(tgh), BF(tgl), BF(tuh), BF(tul),
        BF(lgh), BF(lgl), BF(luh), BF(lul),
        b_gate, b_up,
        nullptr, BF(x3h), BF(x3l), FDIM, DDIM);

    // LoRA-A for down (reads x3 hi/lo)
    lora_a_kernel<<<MTOK / 8, 256>>>(nullptr, BF(x3h), BF(x3l), FDIM, wda, nullptr,
                                     BF(tdh), BF(tdl), nullptr, nullptr);

    // down GEMM -> out (fp32)
    gemm_mma<0><<<dim3(DDIM / 256, MTOK / 128), 256, GEMM_SMEM>>>(
        BF(x3h), BF(x3l),
        BF(wdh), BF(wdl), BF(wdh), BF(wdl),
        BF(tdh), BF(tdl), BF(tdh), BF(tdl),
        BF(ldh), BF(ldl), BF(ldh), BF(ldl),
        b_down, nullptr,
        out, nullptr, nullptr, DDIM, FDIM);
}